// round 7
// baseline (speedup 1.0000x reference)
#include <cuda_runtime.h>
#include <math_constants.h>

// Problem constants
#define B_    32
#define L_    1000
#define NCHAR 256
#define DM    512
#define NH    8
#define DH    64
#define XROWS (NCHAR + L_)   // 1256
#define XPAD  1280           // padded row count (multiple of 64), pad rows zero
#define NI    (NH * B_)      // 256 (h,b) pairs
#define LN10000 9.210340371976184f
#define PE_K  (-LN10000 / (float)DM)

// Split-K factors
#define DSPLIT 8
#define DCHUNK (DM / DSPLIT)      // 64
#define YSPLIT 16
#define YCHUNK (XPAD / YSPLIT)    // 80

// Setup grid layout
#define EMB_BLKS 32               // 8 emb rows each
#define PE_BLKS  125              // 8 pe rows each (125*8 = 1000)
#define SETUP_BLKS (EMB_BLKS + PE_BLKS + 1 + NI)   // 414

// Scratch (device globals: no allocation allowed)
__device__ float g_X  [XPAD * DM];           // [emb(256) ; pe(1000) ; zeros(24)]
__device__ float g_u  [NI * DM];             // U[i=h*32+b][e] = q[b,h] @ Wk_head
__device__ float g_dotp[DSPLIT][NI * XPAD];  // K-split partials of D = U @ X^T * scale
__device__ float g_wr [NI * XPAD];           // WR[i][r] softmax weight rows (pad stays 0)
__device__ float g_yp [YSPLIT][NI * DM];     // K-split partials of Y = WR @ X
__device__ float g_ctx[B_ * DM];             // attention context at last valid position

#define GDS() cudaGridDependencySynchronize()

// ---------------------------------------------------------------------------
// Kernel 1 (merged setup): emb copy / pe rows (rotation recurrence) / pad /
// fused q+u per (h,b).
// ---------------------------------------------------------------------------
__global__ void setup_kernel(const int* __restrict__ data,
                             const int* __restrict__ lengths,
                             const float* __restrict__ emb,
                             const float* __restrict__ Wq,
                             const float* __restrict__ bq,
                             const float* __restrict__ Wk) {
    GDS();
    int blk = blockIdx.x;
    int tid = threadIdx.x;           // 256

    if (blk < EMB_BLKS) {
        // copy 8 emb rows
        int r0 = blk * 8;
        #pragma unroll
        for (int rr = 0; rr < 8; rr++) {
            ((float2*)g_X)[(size_t)(r0 + rr) * 256 + tid] =
                ((const float2*)emb)[(size_t)(r0 + rr) * 256 + tid];
        }
        return;
    }
    if (blk < EMB_BLKS + PE_BLKS) {
        // 8 pe rows via rotation recurrence; thread owns pair tid
        int t0 = (blk - EMB_BLKS) * 8;
        float div = expf((float)(2 * tid) * PE_K);
        float s, c, sd, cd;
        sincosf((float)t0 * div, &s, &c);
        sincosf(div, &sd, &cd);
        #pragma unroll
        for (int rr = 0; rr < 8; rr++) {
            ((float2*)g_X)[(size_t)(NCHAR + t0 + rr) * 256 + tid] = make_float2(s, c);
            float s2 = s * cd + c * sd;
            float c2 = c * cd - s * sd;
            s = s2; c = c2;
        }
        return;
    }
    if (blk == EMB_BLKS + PE_BLKS) {
        // zero pad rows
        for (int r = XROWS; r < XPAD; r++)
            ((float2*)g_X)[(size_t)r * 256 + tid] = make_float2(0.f, 0.f);
        return;
    }

    // --- fused q+u for i ---
    int i = blk - (EMB_BLKS + PE_BLKS + 1);
    int h = i >> 5;                  // i = h*32 + b
    int b = i & 31;
    __shared__ float xs[DM];
    __shared__ float qs[DH];
    int w = tid >> 5, lane = tid & 31;

    int p = lengths[b] - 1;
    if (p < 0) p = 0;
    if (p >= L_) p = L_ - 1;
    int ch = data[(size_t)b * L_ + p] & (NCHAR - 1);

    {
        int e0 = 2 * tid;
        float div = expf((float)e0 * PE_K);
        float s, c;
        sincosf((float)p * div, &s, &c);
        float2 ev = *(const float2*)(emb + (size_t)ch * DM + e0);
        xs[e0]     = ev.x + s;
        xs[e0 + 1] = ev.y + c;
    }
    __syncthreads();

    // qh rows: warp w handles d = w*8 .. w*8+7
    for (int d = w * 8; d < w * 8 + 8; d++) {
        int j = h * DH + d;
        const float* wr = Wq + (size_t)j * DM;
        float s = 0.f;
        #pragma unroll
        for (int e0 = lane * 4; e0 < DM; e0 += 128) {
            float4 a = *(const float4*)(wr + e0);
            float4 x4 = *(const float4*)(xs + e0);
            s += a.x * x4.x + a.y * x4.y + a.z * x4.z + a.w * x4.w;
        }
        #pragma unroll
        for (int off = 16; off; off >>= 1) s += __shfl_xor_sync(0xffffffffu, s, off);
        if (lane == 0) qs[d] = s + bq[j];
    }
    __syncthreads();

    // U row: thread owns 2 consecutive e
    int e0 = tid * 2;
    float a0 = 0.f, a1 = 0.f;
    const float* Wbase = Wk + (size_t)(h * DH) * DM;
    #pragma unroll 8
    for (int d = 0; d < DH; d++) {
        float qd = qs[d];
        float2 wv = *(const float2*)(Wbase + (size_t)d * DM + e0);
        a0 += qd * wv.x;
        a1 += qd * wv.y;
    }
    *(float2*)(g_u + (size_t)i * DM + e0) = make_float2(a0, a1);
}

// ---------------------------------------------------------------------------
// Kernel 2: D partials = U @ X^T (NT GEMM, scaled), K split by DSPLIT.
// Double-buffered. grid (XPAD/64, NI/64, DSPLIT), 256 threads.
// ---------------------------------------------------------------------------
#define BM 64
#define BN 64
#define BK 16
__global__ void d_gemm_kernel() {
    GDS();
    int m0 = blockIdx.y * BM;
    int n0 = blockIdx.x * BN;
    int kb = blockIdx.z * DCHUNK;

    __shared__ float As[2][BK][BM + 4];
    __shared__ float Bs[2][BK][BN + 4];

    int tid  = threadIdx.x;          // 256
    int lrow = tid >> 2;             // 0..63
    int lcol = (tid & 3) * 4;        // 0,4,8,12
    int ty = tid >> 4;               // 0..15
    int tx = tid & 15;               // 0..15

    const float* Aptr = g_u + (size_t)(m0 + lrow) * DM + lcol;
    const float* Bptr = g_X + (size_t)(n0 + lrow) * DM + lcol;

    float4 a_n = *(const float4*)(Aptr + kb);
    float4 b_n = *(const float4*)(Bptr + kb);
    As[0][lcol + 0][lrow] = a_n.x; As[0][lcol + 1][lrow] = a_n.y;
    As[0][lcol + 2][lrow] = a_n.z; As[0][lcol + 3][lrow] = a_n.w;
    Bs[0][lcol + 0][lrow] = b_n.x; Bs[0][lcol + 1][lrow] = b_n.y;
    Bs[0][lcol + 2][lrow] = b_n.z; Bs[0][lcol + 3][lrow] = b_n.w;
    __syncthreads();

    float acc[4][4] = {};
    const int NIT = DCHUNK / BK;     // 4

    for (int it = 0; it < NIT; it++) {
        int cur = it & 1, nxt = cur ^ 1;
        if (it + 1 < NIT) {
            a_n = *(const float4*)(Aptr + kb + (it + 1) * BK);
            b_n = *(const float4*)(Bptr + kb + (it + 1) * BK);
        }
        #pragma unroll
        for (int kk = 0; kk < BK; kk++) {
            float4 a4 = *(const float4*)&As[cur][kk][ty * 4];
            float4 b4 = *(const float4*)&Bs[cur][kk][tx * 4];
            float a[4] = {a4.x, a4.y, a4.z, a4.w};
            float b[4] = {b4.x, b4.y, b4.z, b4.w};
            #pragma unroll
            for (int i = 0; i < 4; i++)
                #pragma unroll
                for (int j = 0; j < 4; j++)
                    acc[i][j] += a[i] * b[j];
        }
        if (it + 1 < NIT) {
            As[nxt][lcol + 0][lrow] = a_n.x; As[nxt][lcol + 1][lrow] = a_n.y;
            As[nxt][lcol + 2][lrow] = a_n.z; As[nxt][lcol + 3][lrow] = a_n.w;
            Bs[nxt][lcol + 0][lrow] = b_n.x; Bs[nxt][lcol + 1][lrow] = b_n.y;
            Bs[nxt][lcol + 2][lrow] = b_n.z; Bs[nxt][lcol + 3][lrow] = b_n.w;
            __syncthreads();
        }
    }

    float* outp = g_dotp[blockIdx.z];
    #pragma unroll
    for (int i = 0; i < 4; i++) {
        int r = m0 + ty * 4 + i;
        #pragma unroll
        for (int j = 0; j < 4; j++) {
            int c = n0 + tx * 4 + j;
            outp[(size_t)r * XPAD + c] = acc[i][j] * 0.125f;  // 1/sqrt(64)
        }
    }
}

// ---------------------------------------------------------------------------
// Kernel 3: per (h,b) softmax over valid positions + char binning.
// ---------------------------------------------------------------------------
__global__ void softmax_bin_kernel(const int* __restrict__ data,
                                   const int* __restrict__ lengths) {
    GDS();
    int h = blockIdx.x;
    int b = blockIdx.y;
    int i = h * B_ + b;
    __shared__ float s[L_];
    __shared__ float dch[NCHAR];
    __shared__ float bins[NCHAR];
    __shared__ float red[8];

    int tid = threadIdx.x;       // 256
    int count = lengths[b];
    if (count < 1) count = 1;
    if (count > L_) count = L_;

    size_t base = (size_t)i * XPAD;

    // summed char dots (coalesced)
    {
        float v = 0.f;
        #pragma unroll
        for (int z = 0; z < DSPLIT; z++) v += g_dotp[z][base + tid];
        dch[tid] = v;
        bins[tid] = 0.f;
    }
    __syncthreads();

    float lm = -CUDART_INF_F;
    for (int t = tid; t < count; t += 256) {
        int c = data[(size_t)b * L_ + t] & (NCHAR - 1);
        float v = dch[c];
        #pragma unroll
        for (int z = 0; z < DSPLIT; z++) v += g_dotp[z][base + NCHAR + t];
        s[t] = v;
        lm = fmaxf(lm, v);
    }
    #pragma unroll
    for (int off = 16; off; off >>= 1) lm = fmaxf(lm, __shfl_xor_sync(0xffffffffu, lm, off));
    if ((tid & 31) == 0) red[tid >> 5] = lm;
    __syncthreads();
    float M = -CUDART_INF_F;
    #pragma unroll
    for (int k = 0; k < 8; k++) M = fmaxf(M, red[k]);
    __syncthreads();

    float ls = 0.f;
    for (int t = tid; t < count; t += 256) {
        float e = __expf(s[t] - M);
        s[t] = e;
        ls += e;
    }
    #pragma unroll
    for (int off = 16; off; off >>= 1) ls += __shfl_xor_sync(0xffffffffu, ls, off);
    if ((tid & 31) == 0) red[tid >> 5] = ls;
    __syncthreads();
    float S = 0.f;
    #pragma unroll
    for (int k = 0; k < 8; k++) S += red[k];
    float inv = 1.f / S;

    float* WR = g_wr + base;
    for (int t = tid; t < L_; t += 256) {
        float w = 0.f;
        if (t < count) {
            w = s[t] * inv;
            atomicAdd(&bins[data[(size_t)b * L_ + t] & (NCHAR - 1)], w);
        }
        WR[NCHAR + t] = w;
    }
    __syncthreads();
    WR[tid] = bins[tid];
    // pad rows of g_X are zero, so WR[XROWS..XPAD) never contributes (stays 0)
}

// ---------------------------------------------------------------------------
// Kernel 4: Y partials = WR @ X (NN GEMM), K split by YSPLIT. Double-buffered.
// grid (DM/64, NI/64, YSPLIT), 256 threads.
// ---------------------------------------------------------------------------
__global__ void y_gemm_kernel() {
    GDS();
    int m0 = blockIdx.y * BM;
    int n0 = blockIdx.x * BN;
    int kb = blockIdx.z * YCHUNK;

    __shared__ float As[2][BK][BM + 4];
    __shared__ float Bs[2][BK][BN + 4];

    int tid  = threadIdx.x;          // 256
    int lrow = tid >> 2;             // 0..63
    int lcol = (tid & 3) * 4;        // 0,4,8,12
    int br = tid >> 4;               // 0..15 (B tile row)
    int bc = (tid & 15) * 4;         // 0..60 (B tile col)
    int ty = tid >> 4;
    int tx = tid & 15;

    const float* Aptr = g_wr + (size_t)(m0 + lrow) * XPAD + lcol;

    float4 a_n = *(const float4*)(Aptr + kb);
    float4 b_n = *(const float4*)(g_X + (size_t)(kb + br) * DM + n0 + bc);
    As[0][lcol + 0][lrow] = a_n.x; As[0][lcol + 1][lrow] = a_n.y;
    As[0][lcol + 2][lrow] = a_n.z; As[0][lcol + 3][lrow] = a_n.w;
    *(float4*)&Bs[0][br][bc] = b_n;
    __syncthreads();

    float acc[4][4] = {};
    const int NIT = YCHUNK / BK;     // 5

    for (int it = 0; it < NIT; it++) {
        int cur = it & 1, nxt = cur ^ 1;
        if (it + 1 < NIT) {
            int k0 = kb + (it + 1) * BK;
            a_n = *(const float4*)(Aptr + k0);
            b_n = *(const float4*)(g_X + (size_t)(k0 + br) * DM + n0 + bc);
        }
        #pragma unroll
        for (int kk = 0; kk < BK; kk++) {
            float4 a4 = *(const float4*)&As[cur][kk][ty * 4];
            float4 b4 = *(const float4*)&Bs[cur][kk][tx * 4];
            float a[4] = {a4.x, a4.y, a4.z, a4.w};
            float b[4] = {b4.x, b4.y, b4.z, b4.w};
            #pragma unroll
            for (int ii = 0; ii < 4; ii++)
                #pragma unroll
                for (int jj = 0; jj < 4; jj++)
                    acc[ii][jj] += a[ii] * b[jj];
        }
        if (it + 1 < NIT) {
            As[nxt][lcol + 0][lrow] = a_n.x; As[nxt][lcol + 1][lrow] = a_n.y;
            As[nxt][lcol + 2][lrow] = a_n.z; As[nxt][lcol + 3][lrow] = a_n.w;
            *(float4*)&Bs[nxt][br][bc] = b_n;
            __syncthreads();
        }
    }

    float* outp = g_yp[blockIdx.z];
    #pragma unroll
    for (int ii = 0; ii < 4; ii++) {
        int r = m0 + ty * 4 + ii;
        #pragma unroll
        for (int jj = 0; jj < 4; jj++)
            outp[(size_t)r * DM + n0 + tx * 4 + jj] = acc[ii][jj];
    }
}

// ---------------------------------------------------------------------------
// Kernel 5: ctx rows for one (h,b): ctx[b][h*64+d] = Wv_h[d] . y + bv.
// ---------------------------------------------------------------------------
__global__ void ctx_kernel(const float* __restrict__ Wv,
                           const float* __restrict__ bv) {
    GDS();
    int h = blockIdx.x, b = blockIdx.y;
    __shared__ float ys[DM];
    int tid = threadIdx.x;           // 256
    int w = tid >> 5, lane = tid & 31;

    if (tid < 128) {
        float4 v = make_float4(0.f, 0.f, 0.f, 0.f);
        size_t off = (size_t)(h * B_ + b) * DM;
        #pragma unroll
        for (int z = 0; z < YSPLIT; z++) {
            float4 p = ((const float4*)(g_yp[z] + off))[tid];
            v.x += p.x; v.y += p.y; v.z += p.z; v.w += p.w;
        }
        ((float4*)ys)[tid] = v;
    }
    __syncthreads();

    #pragma unroll
    for (int jj = 0; jj < 8; jj += 2) {
        int j0 = h * DH + w * 8 + jj;
        const float* w0 = Wv + (size_t)j0 * DM;
        const float* w1 = w0 + DM;
        float s0 = 0.f, s1 = 0.f;
        #pragma unroll
        for (int e0 = lane * 4; e0 < DM; e0 += 128) {
            float4 y4 = *(const float4*)(ys + e0);
            float4 a0 = *(const float4*)(w0 + e0);
            float4 a1 = *(const float4*)(w1 + e0);
            s0 += a0.x * y4.x + a0.y * y4.y + a0.z * y4.z + a0.w * y4.w;
            s1 += a1.x * y4.x + a1.y * y4.y + a1.z * y4.z + a1.w * y4.w;
        }
        #pragma unroll
        for (int off = 16; off; off >>= 1) {
            s0 += __shfl_xor_sync(0xffffffffu, s0, off);
            s1 += __shfl_xor_sync(0xffffffffu, s1, off);
        }
        if (lane == 0) {
            g_ctx[b * DM + j0]     = s0 + bv[j0];
            g_ctx[b * DM + j0 + 1] = s1 + bv[j0 + 1];
        }
    }
}

// ---------------------------------------------------------------------------
// Kernel 6: MLP head per batch.
// ---------------------------------------------------------------------------
__global__ void mlp_kernel(const float* __restrict__ W1,
                           const float* __restrict__ b1,
                           const float* __restrict__ W2,
                           const float* __restrict__ b2,
                           float* __restrict__ out) {
    GDS();
    int b = blockIdx.x;
    __shared__ float cs[DM];
    __shared__ float hs[DM];
    __shared__ float o8[8];
    int tid = threadIdx.x;           // 256
    int w = tid >> 5, lane = tid & 31;

    for (int e = tid; e < DM; e += 256) cs[e] = g_ctx[b * DM + e];
    __syncthreads();

    for (int jj = 0; jj < DH; jj += 2) {
        int j0 = w * DH + jj;
        const float* w0 = W1 + (size_t)j0 * DM;
        const float* w1 = w0 + DM;
        float s0 = 0.f, s1 = 0.f;
        #pragma unroll
        for (int e0 = lane * 4; e0 < DM; e0 += 128) {
            float4 c4 = *(const float4*)(cs + e0);
            float4 a0 = *(const float4*)(w0 + e0);
            float4 a1 = *(const float4*)(w1 + e0);
            s0 += a0.x * c4.x + a0.y * c4.y + a0.z * c4.z + a0.w * c4.w;
            s1 += a1.x * c4.x + a1.y * c4.y + a1.z * c4.z + a1.w * c4.w;
        }
        #pragma unroll
        for (int off = 16; off; off >>= 1) {
            s0 += __shfl_xor_sync(0xffffffffu, s0, off);
            s1 += __shfl_xor_sync(0xffffffffu, s1, off);
        }
        if (lane == 0) {
            float v0 = s0 + b1[j0];
            float v1 = s1 + b1[j0 + 1];
            hs[j0]     = (v0 > 0.f) ? v0 : 0.01f * v0;
            hs[j0 + 1] = (v1 > 0.f) ? v1 : 0.01f * v1;
        }
    }
    __syncthreads();

    {
        const float* wr = W2 + (size_t)w * DM;
        float s = 0.f;
        #pragma unroll
        for (int e0 = lane * 4; e0 < DM; e0 += 128) {
            float4 a = *(const float4*)(wr + e0);
            float4 h4 = *(const float4*)(hs + e0);
            s += a.x * h4.x + a.y * h4.y + a.z * h4.z + a.w * h4.w;
        }
        #pragma unroll
        for (int off = 16; off; off >>= 1) s += __shfl_xor_sync(0xffffffffu, s, off);
        if (lane == 0) {
            float v = s + b2[w];
            o8[w] = (v > 0.f) ? v : 0.f;
        }
    }
    __syncthreads();
    if (tid == 0) {
        float mv = 0.f;
        #pragma unroll
        for (int k = 0; k < 8; k++) mv += o8[k];
        mv *= 0.125f;
        out[b] = (mv > 0.f) ? mv : 0.01f * mv;
    }
}

// ---------------------------------------------------------------------------
// PDL launch helper: overlap each kernel's launch/dispatch with predecessor.
// ---------------------------------------------------------------------------
template <typename F, typename... Args>
static inline void pdl_launch(F f, dim3 g, dim3 b, Args... args) {
    cudaLaunchConfig_t cfg = {};
    cfg.gridDim = g;
    cfg.blockDim = b;
    cfg.dynamicSmemBytes = 0;
    cfg.stream = 0;
    cudaLaunchAttribute at[1];
    at[0].id = cudaLaunchAttributeProgrammaticStreamSerialization;
    at[0].val.programmaticStreamSerializationAllowed = 1;
    cfg.attrs = at;
    cfg.numAttrs = 1;
    cudaLaunchKernelEx(&cfg, f, args...);
}

extern "C" void kernel_launch(void* const* d_in, const int* in_sizes, int n_in,
                              void* d_out, int out_size) {
    const int* data    = (const int*)d_in[0];    // int32 (JAX x64 disabled)
    const int* lengths = (const int*)d_in[1];
    const float* emb = (const float*)d_in[2];
    const float* Wq  = (const float*)d_in[3];
    const float* bq  = (const float*)d_in[4];
    const float* Wk  = (const float*)d_in[5];
    // d_in[6] = bk: drops out of softmax (constant shift per row)
    const float* Wv  = (const float*)d_in[7];
    const float* bv  = (const float*)d_in[8];
    const float* W1  = (const float*)d_in[9];
    const float* b1  = (const float*)d_in[10];
    const float* W2  = (const float*)d_in[11];
    const float* b2  = (const float*)d_in[12];
    float* out = (float*)d_out;

    pdl_launch(setup_kernel, dim3(SETUP_BLKS), dim3(256),
               data, lengths, emb, Wq, bq, Wk);
    pdl_launch(d_gemm_kernel, dim3(XPAD / BN, NI / BM, DSPLIT), dim3(256));
    pdl_launch(softmax_bin_kernel, dim3(NH, B_), dim3(256), data, lengths);
    pdl_launch(y_gemm_kernel, dim3(DM / BN, NI / BM, YSPLIT), dim3(256));
    pdl_launch(ctx_kernel, dim3(NH, B_), dim3(256), Wv, bv);
    pdl_launch(mlp_kernel, dim3(B_), dim3(256), W1, b1, W2, b2, out);
}

// round 8
// speedup vs baseline: 1.2708x; 1.2708x over previous
#include <cuda_runtime.h>
#include <math_constants.h>

// Problem constants
#define B_    32
#define L_    1000
#define NCHAR 256
#define DM    512
#define NH    8
#define DH    64
#define XROWS (NCHAR + L_)   // 1256
#define XPAD  1280           // padded row count (multiple of 64), pad rows zero
#define NI    (NH * B_)      // 256 (h,b) pairs
#define LN10000 9.210340371976184f
#define PE_K  (-LN10000 / (float)DM)

// Split-K factors (R6 values — R7 showed more splitting regresses)
#define DSPLIT 4
#define DCHUNK (DM / DSPLIT)      // 128
#define YSPLIT 8
#define YCHUNK (XPAD / YSPLIT)    // 160

// Setup grid layout
#define EMB_BLKS 32               // 8 emb rows each
#define PE_BLKS  125              // 8 pe rows each (125*8 = 1000)
#define SETUP_BLKS (EMB_BLKS + PE_BLKS + 1 + NI)   // 414

// Scratch (device globals: no allocation allowed)
__device__ float g_X  [XPAD * DM];           // [emb(256) ; pe(1000) ; zeros(24)]
__device__ float g_u  [NI * DM];             // U[i=h*32+b][e] = q[b,h] @ Wk_head
__device__ float g_dotp[DSPLIT][NI * XPAD];  // K-split partials of D = U @ X^T * scale
__device__ float g_wr [NI * XPAD];           // WR[i][r] softmax weight rows (pad stays 0)
__device__ float g_yp [YSPLIT][NI * DM];     // K-split partials of Y = WR @ X

// ---------------------------------------------------------------------------
// Kernel 1 (merged setup): emb copy / pe rows (rotation recurrence) / pad /
// fused q+u per (h,b).
// ---------------------------------------------------------------------------
__global__ void setup_kernel(const int* __restrict__ data,
                             const int* __restrict__ lengths,
                             const float* __restrict__ emb,
                             const float* __restrict__ Wq,
                             const float* __restrict__ bq,
                             const float* __restrict__ Wk) {
    int blk = blockIdx.x;
    int tid = threadIdx.x;           // 256

    if (blk < EMB_BLKS) {
        int r0 = blk * 8;
        #pragma unroll
        for (int rr = 0; rr < 8; rr++) {
            ((float2*)g_X)[(size_t)(r0 + rr) * 256 + tid] =
                ((const float2*)emb)[(size_t)(r0 + rr) * 256 + tid];
        }
        return;
    }
    if (blk < EMB_BLKS + PE_BLKS) {
        // 8 pe rows via rotation recurrence; thread owns pair tid
        int t0 = (blk - EMB_BLKS) * 8;
        float div = expf((float)(2 * tid) * PE_K);
        float s, c, sd, cd;
        sincosf((float)t0 * div, &s, &c);
        sincosf(div, &sd, &cd);
        #pragma unroll
        for (int rr = 0; rr < 8; rr++) {
            ((float2*)g_X)[(size_t)(NCHAR + t0 + rr) * 256 + tid] = make_float2(s, c);
            float s2 = s * cd + c * sd;
            float c2 = c * cd - s * sd;
            s = s2; c = c2;
        }
        return;
    }
    if (blk == EMB_BLKS + PE_BLKS) {
        for (int r = XROWS; r < XPAD; r++)
            ((float2*)g_X)[(size_t)r * 256 + tid] = make_float2(0.f, 0.f);
        return;
    }

    // --- fused q+u for i ---
    int i = blk - (EMB_BLKS + PE_BLKS + 1);
    int h = i >> 5;                  // i = h*32 + b
    int b = i & 31;
    __shared__ float xs[DM];
    __shared__ float qs[DH];
    int w = tid >> 5, lane = tid & 31;

    int p = lengths[b] - 1;
    if (p < 0) p = 0;
    if (p >= L_) p = L_ - 1;
    int ch = data[(size_t)b * L_ + p] & (NCHAR - 1);

    {
        int e0 = 2 * tid;
        float div = expf((float)e0 * PE_K);
        float s, c;
        sincosf((float)p * div, &s, &c);
        float2 ev = *(const float2*)(emb + (size_t)ch * DM + e0);
        xs[e0]     = ev.x + s;
        xs[e0 + 1] = ev.y + c;
    }
    __syncthreads();

    for (int d = w * 8; d < w * 8 + 8; d++) {
        int j = h * DH + d;
        const float* wr = Wq + (size_t)j * DM;
        float s = 0.f;
        #pragma unroll
        for (int e0 = lane * 4; e0 < DM; e0 += 128) {
            float4 a = *(const float4*)(wr + e0);
            float4 x4 = *(const float4*)(xs + e0);
            s += a.x * x4.x + a.y * x4.y + a.z * x4.z + a.w * x4.w;
        }
        #pragma unroll
        for (int off = 16; off; off >>= 1) s += __shfl_xor_sync(0xffffffffu, s, off);
        if (lane == 0) qs[d] = s + bq[j];
    }
    __syncthreads();

    int e0 = tid * 2;
    float a0 = 0.f, a1 = 0.f;
    const float* Wbase = Wk + (size_t)(h * DH) * DM;
    #pragma unroll 8
    for (int d = 0; d < DH; d++) {
        float qd = qs[d];
        float2 wv = *(const float2*)(Wbase + (size_t)d * DM + e0);
        a0 += qd * wv.x;
        a1 += qd * wv.y;
    }
    *(float2*)(g_u + (size_t)i * DM + e0) = make_float2(a0, a1);
}

// ---------------------------------------------------------------------------
// Kernel 2: D partials = U @ X^T (NT GEMM, scaled), K split by DSPLIT.
// 128 threads, 64x64 tile, 8x4 per-thread registers, double-buffered.
// ---------------------------------------------------------------------------
#define BM 64
#define BN 64
#define BK 16
__global__ void d_gemm_kernel() {
    int m0 = blockIdx.y * BM;
    int n0 = blockIdx.x * BN;
    int kb = blockIdx.z * DCHUNK;

    __shared__ float As[2][BK][BM + 4];
    __shared__ float Bs[2][BK][BN + 4];

    int tid = threadIdx.x;           // 128
    // two float4 loads per tile per array: elems [tid*4] and [tid*4+512]
    int r0_ = (tid * 4) >> 4,        c0_ = (tid * 4) & 15;
    int r1_ = (tid * 4 + 512) >> 4,  c1_ = (tid * 4 + 512) & 15;

    int ty = tid >> 4;               // 0..7  -> rows ty*8 .. ty*8+7
    int tx = tid & 15;               // 0..15 -> cols tx*4 .. tx*4+3

    const float* A0 = g_u + (size_t)(m0 + r0_) * DM + c0_;
    const float* A1 = g_u + (size_t)(m0 + r1_) * DM + c1_;
    const float* B0 = g_X + (size_t)(n0 + r0_) * DM + c0_;
    const float* B1 = g_X + (size_t)(n0 + r1_) * DM + c1_;

    float4 a_n0 = *(const float4*)(A0 + kb);
    float4 a_n1 = *(const float4*)(A1 + kb);
    float4 b_n0 = *(const float4*)(B0 + kb);
    float4 b_n1 = *(const float4*)(B1 + kb);
    #pragma unroll
    for (int q = 0; q < 4; q++) {
        As[0][c0_ + q][r0_] = ((const float*)&a_n0)[q];
        As[0][c1_ + q][r1_] = ((const float*)&a_n1)[q];
        Bs[0][c0_ + q][r0_] = ((const float*)&b_n0)[q];
        Bs[0][c1_ + q][r1_] = ((const float*)&b_n1)[q];
    }
    __syncthreads();

    float acc[8][4] = {};
    const int NIT = DCHUNK / BK;     // 8

    for (int it = 0; it < NIT; it++) {
        int cur = it & 1, nxt = cur ^ 1;
        if (it + 1 < NIT) {
            int k0 = kb + (it + 1) * BK;
            a_n0 = *(const float4*)(A0 + k0);
            a_n1 = *(const float4*)(A1 + k0);
            b_n0 = *(const float4*)(B0 + k0);
            b_n1 = *(const float4*)(B1 + k0);
        }
        #pragma unroll
        for (int kk = 0; kk < BK; kk++) {
            float4 av0 = *(const float4*)&As[cur][kk][ty * 8];
            float4 av1 = *(const float4*)&As[cur][kk][ty * 8 + 4];
            float4 bv  = *(const float4*)&Bs[cur][kk][tx * 4];
            float a[8] = {av0.x, av0.y, av0.z, av0.w, av1.x, av1.y, av1.z, av1.w};
            float bb[4] = {bv.x, bv.y, bv.z, bv.w};
            #pragma unroll
            for (int i = 0; i < 8; i++)
                #pragma unroll
                for (int j = 0; j < 4; j++)
                    acc[i][j] += a[i] * bb[j];
        }
        if (it + 1 < NIT) {
            #pragma unroll
            for (int q = 0; q < 4; q++) {
                As[nxt][c0_ + q][r0_] = ((const float*)&a_n0)[q];
                As[nxt][c1_ + q][r1_] = ((const float*)&a_n1)[q];
                Bs[nxt][c0_ + q][r0_] = ((const float*)&b_n0)[q];
                Bs[nxt][c1_ + q][r1_] = ((const float*)&b_n1)[q];
            }
            __syncthreads();
        }
    }

    float* outp = g_dotp[blockIdx.z];
    #pragma unroll
    for (int i = 0; i < 8; i++) {
        int r = m0 + ty * 8 + i;
        float4 v = make_float4(acc[i][0] * 0.125f, acc[i][1] * 0.125f,
                               acc[i][2] * 0.125f, acc[i][3] * 0.125f);
        *(float4*)(outp + (size_t)r * XPAD + n0 + tx * 4) = v;
    }
}

// ---------------------------------------------------------------------------
// Kernel 3: per (h,b) softmax over valid positions + char binning.
// ---------------------------------------------------------------------------
__global__ void softmax_bin_kernel(const int* __restrict__ data,
                                   const int* __restrict__ lengths) {
    int h = blockIdx.x;
    int b = blockIdx.y;
    int i = h * B_ + b;
    __shared__ float s[L_];
    __shared__ float dch[NCHAR];
    __shared__ float bins[NCHAR];
    __shared__ float red[8];

    int tid = threadIdx.x;       // 256
    int count = lengths[b];
    if (count < 1) count = 1;
    if (count > L_) count = L_;

    size_t base = (size_t)i * XPAD;

    {
        float v = 0.f;
        #pragma unroll
        for (int z = 0; z < DSPLIT; z++) v += g_dotp[z][base + tid];
        dch[tid] = v;
        bins[tid] = 0.f;
    }
    __syncthreads();

    float lm = -CUDART_INF_F;
    for (int t = tid; t < count; t += 256) {
        int c = data[(size_t)b * L_ + t] & (NCHAR - 1);
        float v = dch[c];
        #pragma unroll
        for (int z = 0; z < DSPLIT; z++) v += g_dotp[z][base + NCHAR + t];
        s[t] = v;
        lm = fmaxf(lm, v);
    }
    #pragma unroll
    for (int off = 16; off; off >>= 1) lm = fmaxf(lm, __shfl_xor_sync(0xffffffffu, lm, off));
    if ((tid & 31) == 0) red[tid >> 5] = lm;
    __syncthreads();
    float M = -CUDART_INF_F;
    #pragma unroll
    for (int k = 0; k < 8; k++) M = fmaxf(M, red[k]);
    __syncthreads();

    float ls = 0.f;
    for (int t = tid; t < count; t += 256) {
        float e = __expf(s[t] - M);
        s[t] = e;
        ls += e;
    }
    #pragma unroll
    for (int off = 16; off; off >>= 1) ls += __shfl_xor_sync(0xffffffffu, ls, off);
    if ((tid & 31) == 0) red[tid >> 5] = ls;
    __syncthreads();
    float S = 0.f;
    #pragma unroll
    for (int k = 0; k < 8; k++) S += red[k];
    float inv = 1.f / S;

    float* WR = g_wr + base;
    for (int t = tid; t < L_; t += 256) {
        float w = 0.f;
        if (t < count) {
            w = s[t] * inv;
            atomicAdd(&bins[data[(size_t)b * L_ + t] & (NCHAR - 1)], w);
        }
        WR[NCHAR + t] = w;
    }
    __syncthreads();
    WR[tid] = bins[tid];
    // pad rows of g_X are zero, so WR[XROWS..XPAD) never contributes (stays 0)
}

// ---------------------------------------------------------------------------
// Kernel 4: Y partials = WR @ X (NN GEMM), K split by YSPLIT.
// 128 threads, 64x64 tile, 8x4 per-thread registers, double-buffered.
// ---------------------------------------------------------------------------
__global__ void y_gemm_kernel() {
    int m0 = blockIdx.y * BM;
    int n0 = blockIdx.x * BN;
    int kb = blockIdx.z * YCHUNK;

    __shared__ float As[2][BK][BM + 4];
    __shared__ float Bs[2][BK][BN + 4];

    int tid = threadIdx.x;           // 128
    // A loader (transpose): rows of WR x K
    int ar0 = (tid * 4) >> 4,       ac0 = (tid * 4) & 15;
    int ar1 = (tid * 4 + 512) >> 4, ac1 = (tid * 4 + 512) & 15;
    // B loader (direct): K rows x N cols
    int br0 = (tid * 4) >> 6,       bc0 = (tid * 4) & 63;
    int br1 = (tid * 4 + 512) >> 6, bc1 = (tid * 4 + 512) & 63;

    int ty = tid >> 4;               // 0..7
    int tx = tid & 15;               // 0..15

    const float* A0 = g_wr + (size_t)(m0 + ar0) * XPAD + ac0;
    const float* A1 = g_wr + (size_t)(m0 + ar1) * XPAD + ac1;

    float4 a_n0 = *(const float4*)(A0 + kb);
    float4 a_n1 = *(const float4*)(A1 + kb);
    float4 b_n0 = *(const float4*)(g_X + (size_t)(kb + br0) * DM + n0 + bc0);
    float4 b_n1 = *(const float4*)(g_X + (size_t)(kb + br1) * DM + n0 + bc1);
    #pragma unroll
    for (int q = 0; q < 4; q++) {
        As[0][ac0 + q][ar0] = ((const float*)&a_n0)[q];
        As[0][ac1 + q][ar1] = ((const float*)&a_n1)[q];
    }
    *(float4*)&Bs[0][br0][bc0] = b_n0;
    *(float4*)&Bs[0][br1][bc1] = b_n1;
    __syncthreads();

    float acc[8][4] = {};
    const int NIT = YCHUNK / BK;     // 10

    for (int it = 0; it < NIT; it++) {
        int cur = it & 1, nxt = cur ^ 1;
        if (it + 1 < NIT) {
            int k0 = kb + (it + 1) * BK;
            a_n0 = *(const float4*)(A0 + k0);
            a_n1 = *(const float4*)(A1 + k0);
            b_n0 = *(const float4*)(g_X + (size_t)(k0 + br0) * DM + n0 + bc0);
            b_n1 = *(const float4*)(g_X + (size_t)(k0 + br1) * DM + n0 + bc1);
        }
        #pragma unroll
        for (int kk = 0; kk < BK; kk++) {
            float4 av0 = *(const float4*)&As[cur][kk][ty * 8];
            float4 av1 = *(const float4*)&As[cur][kk][ty * 8 + 4];
            float4 bv  = *(const float4*)&Bs[cur][kk][tx * 4];
            float a[8] = {av0.x, av0.y, av0.z, av0.w, av1.x, av1.y, av1.z, av1.w};
            float bb[4] = {bv.x, bv.y, bv.z, bv.w};
            #pragma unroll
            for (int i = 0; i < 8; i++)
                #pragma unroll
                for (int j = 0; j < 4; j++)
                    acc[i][j] += a[i] * bb[j];
        }
        if (it + 1 < NIT) {
            #pragma unroll
            for (int q = 0; q < 4; q++) {
                As[nxt][ac0 + q][ar0] = ((const float*)&a_n0)[q];
                As[nxt][ac1 + q][ar1] = ((const float*)&a_n1)[q];
            }
            *(float4*)&Bs[nxt][br0][bc0] = b_n0;
            *(float4*)&Bs[nxt][br1][bc1] = b_n1;
            __syncthreads();
        }
    }

    float* outp = g_yp[blockIdx.z];
    #pragma unroll
    for (int i = 0; i < 8; i++) {
        int r = m0 + ty * 8 + i;
        *(float4*)(outp + (size_t)r * DM + n0 + tx * 4) =
            make_float4(acc[i][0], acc[i][1], acc[i][2], acc[i][3]);
    }
}

// ---------------------------------------------------------------------------
// Kernel 5 (fused): sum Y partials; ctx = per-head Wv_h @ y + bv; MLP head.
// One block per batch, 256 threads (8 warps). Warp w == head w.
// ---------------------------------------------------------------------------
__global__ void ctx_mlp_kernel(const float* __restrict__ Wv,
                               const float* __restrict__ bv,
                               const float* __restrict__ W1,
                               const float* __restrict__ b1,
                               const float* __restrict__ W2,
                               const float* __restrict__ b2,
                               float* __restrict__ out) {
    int b = blockIdx.x;
    __shared__ float ys[NH][DM];     // 16 KB
    __shared__ float cs[DM];
    __shared__ float hs[DM];
    __shared__ float o8[8];
    int tid = threadIdx.x;           // 256
    int w = tid >> 5, lane = tid & 31;

    // stage y for all 8 heads (sum YSPLIT partials), float4 granularity
    for (int i4 = tid; i4 < NH * DM / 4; i4 += 256) {
        int h = i4 >> 7;             // 128 float4 per head
        int e4 = i4 & 127;
        float4 v = make_float4(0.f, 0.f, 0.f, 0.f);
        size_t off4 = ((size_t)(h * B_ + b) * DM) / 4 + e4;
        #pragma unroll
        for (int z = 0; z < YSPLIT; z++) {
            float4 p = ((const float4*)g_yp[z])[off4];
            v.x += p.x; v.y += p.y; v.z += p.z; v.w += p.w;
        }
        ((float4*)ys[h])[e4] = v;
    }
    __syncthreads();

    // ctx rows: warp w handles head w (rows w*64 .. w*64+63), dual-row
    const float* yv = ys[w];
    for (int jj = 0; jj < DH; jj += 2) {
        int j0 = w * DH + jj;
        const float* w0 = Wv + (size_t)j0 * DM;
        const float* w1 = w0 + DM;
        float s0 = 0.f, s1 = 0.f;
        #pragma unroll
        for (int e0 = lane * 4; e0 < DM; e0 += 128) {
            float4 y4 = *(const float4*)(yv + e0);
            float4 a0 = *(const float4*)(w0 + e0);
            float4 a1 = *(const float4*)(w1 + e0);
            s0 += a0.x * y4.x + a0.y * y4.y + a0.z * y4.z + a0.w * y4.w;
            s1 += a1.x * y4.x + a1.y * y4.y + a1.z * y4.z + a1.w * y4.w;
        }
        #pragma unroll
        for (int off = 16; off; off >>= 1) {
            s0 += __shfl_xor_sync(0xffffffffu, s0, off);
            s1 += __shfl_xor_sync(0xffffffffu, s1, off);
        }
        if (lane == 0) {
            cs[j0]     = s0 + bv[j0];
            cs[j0 + 1] = s1 + bv[j0 + 1];
        }
    }
    __syncthreads();

    // layer 1: hs = lrelu(W1 @ cs + b1), dual-row
    for (int jj = 0; jj < DH; jj += 2) {
        int j0 = w * DH + jj;
        const float* w0 = W1 + (size_t)j0 * DM;
        const float* w1 = w0 + DM;
        float s0 = 0.f, s1 = 0.f;
        #pragma unroll
        for (int e0 = lane * 4; e0 < DM; e0 += 128) {
            float4 c4 = *(const float4*)(cs + e0);
            float4 a0 = *(const float4*)(w0 + e0);
            float4 a1 = *(const float4*)(w1 + e0);
            s0 += a0.x * c4.x + a0.y * c4.y + a0.z * c4.z + a0.w * c4.w;
            s1 += a1.x * c4.x + a1.y * c4.y + a1.z * c4.z + a1.w * c4.w;
        }
        #pragma unroll
        for (int off = 16; off; off >>= 1) {
            s0 += __shfl_xor_sync(0xffffffffu, s0, off);
            s1 += __shfl_xor_sync(0xffffffffu, s1, off);
        }
        if (lane == 0) {
            float v0 = s0 + b1[j0];
            float v1 = s1 + b1[j0 + 1];
            hs[j0]     = (v0 > 0.f) ? v0 : 0.01f * v0;
            hs[j0 + 1] = (v1 > 0.f) ? v1 : 0.01f * v1;
        }
    }
    __syncthreads();

    // layer 2: warp w -> output row w
    {
        const float* wr = W2 + (size_t)w * DM;
        float s = 0.f;
        #pragma unroll
        for (int e0 = lane * 4; e0 < DM; e0 += 128) {
            float4 a = *(const float4*)(wr + e0);
            float4 h4 = *(const float4*)(hs + e0);
            s += a.x * h4.x + a.y * h4.y + a.z * h4.z + a.w * h4.w;
        }
        #pragma unroll
        for (int off = 16; off; off >>= 1) s += __shfl_xor_sync(0xffffffffu, s, off);
        if (lane == 0) {
            float v = s + b2[w];
            o8[w] = (v > 0.f) ? v : 0.f;
        }
    }
    __syncthreads();
    if (tid == 0) {
        float mv = 0.f;
        #pragma unroll
        for (int k = 0; k < 8; k++) mv += o8[k];
        mv *= 0.125f;
        out[b] = (mv > 0.f) ? mv : 0.01f * mv;
    }
}

// ---------------------------------------------------------------------------
extern "C" void kernel_launch(void* const* d_in, const int* in_sizes, int n_in,
                              void* d_out, int out_size) {
    const int* data    = (const int*)d_in[0];    // int32 (JAX x64 disabled)
    const int* lengths = (const int*)d_in[1];
    const float* emb = (const float*)d_in[2];
    const float* Wq  = (const float*)d_in[3];
    const float* bq  = (const float*)d_in[4];
    const float* Wk  = (const float*)d_in[5];
    // d_in[6] = bk: drops out of softmax (constant shift per row)
    const float* Wv  = (const float*)d_in[7];
    const float* bv  = (const float*)d_in[8];
    const float* W1  = (const float*)d_in[9];
    const float* b1  = (const float*)d_in[10];
    const float* W2  = (const float*)d_in[11];
    const float* b2  = (const float*)d_in[12];
    float* out = (float*)d_out;

    setup_kernel<<<SETUP_BLKS, 256>>>(data, lengths, emb, Wq, bq, Wk);
    d_gemm_kernel<<<dim3(XPAD / BN, NI / BM, DSPLIT), 128>>>();
    softmax_bin_kernel<<<dim3(NH, B_), 256>>>(data, lengths);
    y_gemm_kernel<<<dim3(DM / BN, NI / BM, YSPLIT), 128>>>();
    ctx_mlp_kernel<<<B_, 256>>>(Wv, bv, W1, b1, W2, b2, out);
}

// round 12
// speedup vs baseline: 1.4029x; 1.1039x over previous
#include <cuda_runtime.h>
#include <math_constants.h>

// Problem constants
#define B_    32
#define L_    1000
#define NCHAR 256
#define DM    512
#define NH    8
#define DH    64
#define XROWS (NCHAR + L_)   // 1256
#define XPAD  1280           // padded row count (multiple of 64), pad rows zero
#define NI    (NH * B_)      // 256 (h,b) pairs
#define LN10000 9.210340371976184f
#define PE_K  (-LN10000 / (float)DM)

// Split-K factors (R6 values — proven best)
#define DSPLIT 4
#define YSPLIT 8
#define DCHUNK (DM / DSPLIT)      // 128
#define YCHUNK (XPAD / YSPLIT)    // 160

// Megakernel geometry
#define NBLK 320                  // == d_gemm logical grid (largest stage)

// Setup stage logical layout
#define EMB_BLKS 32               // 8 emb rows each
#define PE_BLKS  125              // 8 pe rows each
#define SETUP_BLKS (EMB_BLKS + PE_BLKS + 1 + NI)   // 414

// Scratch (device globals: no allocation allowed)
__device__ float g_X  [XPAD * DM];
__device__ float g_u  [NI * DM];
__device__ float g_dotp[DSPLIT][NI * XPAD];
__device__ float g_wr [NI * XPAD];
__device__ float g_yp [YSPLIT][NI * DM];

// Grid barrier state
__device__ unsigned g_bar_count = 0;
__device__ volatile unsigned g_bar_gen = 0;

// Shared memory union (max member 20512 B)
struct GemmSM { float As[2][16][68]; float Bs[2][16][68]; };               // 17408
struct SoftSM { float s[L_]; float dch[NCHAR]; float bins[NCHAR]; float red[8]; }; // 6080
struct CtxSM  { float ys[NH][DM]; float cs[DM]; float hs[DM]; float o8[8]; };      // 20512
struct QuSM   { float xs[DM]; float qs[DH]; };                             // 2304
union SMu { GemmSM g; SoftSM sm; CtxSM cm; QuSM qu; };

__device__ __forceinline__ void grid_barrier() {
    __syncthreads();
    if (threadIdx.x == 0) {
        unsigned gen = g_bar_gen;
        __threadfence();
        if (atomicAdd(&g_bar_count, 1) == NBLK - 1) {
            g_bar_count = 0;
            __threadfence();
            g_bar_gen = gen + 1;
        } else {
            while (g_bar_gen == gen) __nanosleep(32);
        }
        __threadfence();
    }
    __syncthreads();
}

// ---------------------------------------------------------------------------
// Stage A: build X rows / pad / fused q+u
// ---------------------------------------------------------------------------
__device__ __forceinline__ void stage_setup(int lb, int tid, SMu& u,
                                            const int* __restrict__ data,
                                            const int* __restrict__ lengths,
                                            const float* __restrict__ emb,
                                            const float* __restrict__ Wq,
                                            const float* __restrict__ bq,
                                            const float* __restrict__ Wk) {
    if (lb < EMB_BLKS) {
        int r0 = lb * 8;
        #pragma unroll
        for (int rr = 0; rr < 8; rr++)
            ((float2*)g_X)[(size_t)(r0 + rr) * 256 + tid] =
                ((const float2*)emb)[(size_t)(r0 + rr) * 256 + tid];
        return;
    }
    if (lb < EMB_BLKS + PE_BLKS) {
        int t0 = (lb - EMB_BLKS) * 8;
        float div = expf((float)(2 * tid) * PE_K);
        float s, c, sd, cd;
        sincosf((float)t0 * div, &s, &c);
        sincosf(div, &sd, &cd);
        #pragma unroll
        for (int rr = 0; rr < 8; rr++) {
            ((float2*)g_X)[(size_t)(NCHAR + t0 + rr) * 256 + tid] = make_float2(s, c);
            float s2 = s * cd + c * sd;
            float c2 = c * cd - s * sd;
            s = s2; c = c2;
        }
        return;
    }
    if (lb == EMB_BLKS + PE_BLKS) {
        for (int r = XROWS; r < XPAD; r++)
            ((float2*)g_X)[(size_t)r * 256 + tid] = make_float2(0.f, 0.f);
        return;
    }

    int i = lb - (EMB_BLKS + PE_BLKS + 1);
    int h = i >> 5, b = i & 31;
    int w = tid >> 5, lane = tid & 31;

    int p = lengths[b] - 1;
    if (p < 0) p = 0;
    if (p >= L_) p = L_ - 1;
    int ch = data[(size_t)b * L_ + p] & (NCHAR - 1);

    {
        int e0 = 2 * tid;
        float div = expf((float)e0 * PE_K);
        float s, c;
        sincosf((float)p * div, &s, &c);
        float2 ev = *(const float2*)(emb + (size_t)ch * DM + e0);
        u.qu.xs[e0]     = ev.x + s;
        u.qu.xs[e0 + 1] = ev.y + c;
    }
    __syncthreads();

    for (int d = w * 8; d < w * 8 + 8; d++) {
        int j = h * DH + d;
        const float* wr = Wq + (size_t)j * DM;
        float s = 0.f;
        #pragma unroll
        for (int e0 = lane * 4; e0 < DM; e0 += 128) {
            float4 a = *(const float4*)(wr + e0);
            float4 x4 = *(const float4*)(u.qu.xs + e0);
            s += a.x * x4.x + a.y * x4.y + a.z * x4.z + a.w * x4.w;
        }
        #pragma unroll
        for (int off = 16; off; off >>= 1) s += __shfl_xor_sync(0xffffffffu, s, off);
        if (lane == 0) u.qu.qs[d] = s + bq[j];
    }
    __syncthreads();

    int e0 = tid * 2;
    float a0 = 0.f, a1 = 0.f;
    const float* Wbase = Wk + (size_t)(h * DH) * DM;
    #pragma unroll 8
    for (int d = 0; d < DH; d++) {
        float qd = u.qu.qs[d];
        float2 wv = *(const float2*)(Wbase + (size_t)d * DM + e0);
        a0 += qd * wv.x;
        a1 += qd * wv.y;
    }
    *(float2*)(g_u + (size_t)i * DM + e0) = make_float2(a0, a1);
    __syncthreads();   // protect smem for a possible next loop iteration
}

// ---------------------------------------------------------------------------
// Stage B: D partials = U @ X^T (NT), 256 thr, 4x4 tile, double-buffered
// ---------------------------------------------------------------------------
__device__ __forceinline__ void stage_dgemm(int lb, int tid, SMu& u) {
    int z = lb / 80;
    int rem = lb % 80;
    int m0 = (rem / 20) * 64;
    int n0 = (rem % 20) * 64;
    int kb = z * DCHUNK;

    int lrow = tid >> 2;
    int lcol = (tid & 3) * 4;
    int ty = tid >> 4;
    int tx = tid & 15;

    const float* Aptr = g_u + (size_t)(m0 + lrow) * DM + lcol;
    const float* Bptr = g_X + (size_t)(n0 + lrow) * DM + lcol;

    float4 a_n = *(const float4*)(Aptr + kb);
    float4 b_n = *(const float4*)(Bptr + kb);
    #pragma unroll
    for (int q = 0; q < 4; q++) {
        u.g.As[0][lcol + q][lrow] = ((const float*)&a_n)[q];
        u.g.Bs[0][lcol + q][lrow] = ((const float*)&b_n)[q];
    }
    __syncthreads();

    float acc[4][4] = {};
    const int NIT = DCHUNK / 16;     // 8

    for (int it = 0; it < NIT; it++) {
        int cur = it & 1, nxt = cur ^ 1;
        if (it + 1 < NIT) {
            a_n = *(const float4*)(Aptr + kb + (it + 1) * 16);
            b_n = *(const float4*)(Bptr + kb + (it + 1) * 16);
        }
        #pragma unroll
        for (int kk = 0; kk < 16; kk++) {
            float4 a4 = *(const float4*)&u.g.As[cur][kk][ty * 4];
            float4 b4 = *(const float4*)&u.g.Bs[cur][kk][tx * 4];
            float a[4] = {a4.x, a4.y, a4.z, a4.w};
            float b[4] = {b4.x, b4.y, b4.z, b4.w};
            #pragma unroll
            for (int i = 0; i < 4; i++)
                #pragma unroll
                for (int j = 0; j < 4; j++)
                    acc[i][j] += a[i] * b[j];
        }
        if (it + 1 < NIT) {
            #pragma unroll
            for (int q = 0; q < 4; q++) {
                u.g.As[nxt][lcol + q][lrow] = ((const float*)&a_n)[q];
                u.g.Bs[nxt][lcol + q][lrow] = ((const float*)&b_n)[q];
            }
            __syncthreads();
        }
    }

    float* outp = g_dotp[z];
    #pragma unroll
    for (int i = 0; i < 4; i++) {
        int r = m0 + ty * 4 + i;
        #pragma unroll
        for (int j = 0; j < 4; j++)
            outp[(size_t)r * XPAD + n0 + tx * 4 + j] = acc[i][j] * 0.125f;
    }
}

// ---------------------------------------------------------------------------
// Stage C: per (h,b) softmax + char binning
// ---------------------------------------------------------------------------
__device__ __forceinline__ void stage_softmax(int lb, int tid, SMu& u,
                                              const int* __restrict__ data,
                                              const int* __restrict__ lengths) {
    int h = lb >> 5;
    int b = lb & 31;
    int i = h * B_ + b;

    int count = lengths[b];
    if (count < 1) count = 1;
    if (count > L_) count = L_;

    size_t base = (size_t)i * XPAD;

    {
        float v = 0.f;
        #pragma unroll
        for (int z = 0; z < DSPLIT; z++) v += g_dotp[z][base + tid];
        u.sm.dch[tid] = v;
        u.sm.bins[tid] = 0.f;
    }
    __syncthreads();

    float lm = -CUDART_INF_F;
    for (int t = tid; t < count; t += 256) {
        int c = data[(size_t)b * L_ + t] & (NCHAR - 1);
        float v = u.sm.dch[c];
        #pragma unroll
        for (int z = 0; z < DSPLIT; z++) v += g_dotp[z][base + NCHAR + t];
        u.sm.s[t] = v;
        lm = fmaxf(lm, v);
    }
    #pragma unroll
    for (int off = 16; off; off >>= 1) lm = fmaxf(lm, __shfl_xor_sync(0xffffffffu, lm, off));
    if ((tid & 31) == 0) u.sm.red[tid >> 5] = lm;
    __syncthreads();
    float M = -CUDART_INF_F;
    #pragma unroll
    for (int k = 0; k < 8; k++) M = fmaxf(M, u.sm.red[k]);
    __syncthreads();

    float ls = 0.f;
    for (int t = tid; t < count; t += 256) {
        float e = __expf(u.sm.s[t] - M);
        u.sm.s[t] = e;
        ls += e;
    }
    #pragma unroll
    for (int off = 16; off; off >>= 1) ls += __shfl_xor_sync(0xffffffffu, ls, off);
    if ((tid & 31) == 0) u.sm.red[tid >> 5] = ls;
    __syncthreads();
    float S = 0.f;
    #pragma unroll
    for (int k = 0; k < 8; k++) S += u.sm.red[k];
    float inv = 1.f / S;

    float* WR = g_wr + base;
    for (int t = tid; t < L_; t += 256) {
        float w = 0.f;
        if (t < count) {
            w = u.sm.s[t] * inv;
            atomicAdd(&u.sm.bins[data[(size_t)b * L_ + t] & (NCHAR - 1)], w);
        }
        WR[NCHAR + t] = w;
    }
    __syncthreads();
    WR[tid] = u.sm.bins[tid];
}

// ---------------------------------------------------------------------------
// Stage D: Y partials = WR @ X (NN), 256 thr, 4x4 tile, double-buffered
// ---------------------------------------------------------------------------
__device__ __forceinline__ void stage_ygemm(int lb, int tid, SMu& u) {
    int z = lb / 32;
    int rem = lb % 32;
    int m0 = (rem / 8) * 64;
    int n0 = (rem % 8) * 64;
    int kb = z * YCHUNK;

    int lrow = tid >> 2;
    int lcol = (tid & 3) * 4;
    int br = tid >> 4;
    int bc = (tid & 15) * 4;
    int ty = tid >> 4;
    int tx = tid & 15;

    const float* Aptr = g_wr + (size_t)(m0 + lrow) * XPAD + lcol;

    float4 a_n = *(const float4*)(Aptr + kb);
    float4 b_n = *(const float4*)(g_X + (size_t)(kb + br) * DM + n0 + bc);
    #pragma unroll
    for (int q = 0; q < 4; q++)
        u.g.As[0][lcol + q][lrow] = ((const float*)&a_n)[q];
    *(float4*)&u.g.Bs[0][br][bc] = b_n;
    __syncthreads();

    float acc[4][4] = {};
    const int NIT = YCHUNK / 16;     // 10

    for (int it = 0; it < NIT; it++) {
        int cur = it & 1, nxt = cur ^ 1;
        if (it + 1 < NIT) {
            int k0 = kb + (it + 1) * 16;
            a_n = *(const float4*)(Aptr + k0);
            b_n = *(const float4*)(g_X + (size_t)(k0 + br) * DM + n0 + bc);
        }
        #pragma unroll
        for (int kk = 0; kk < 16; kk++) {
            float4 a4 = *(const float4*)&u.g.As[cur][kk][ty * 4];
            float4 b4 = *(const float4*)&u.g.Bs[cur][kk][tx * 4];
            float a[4] = {a4.x, a4.y, a4.z, a4.w};
            float b[4] = {b4.x, b4.y, b4.z, b4.w};
            #pragma unroll
            for (int ii = 0; ii < 4; ii++)
                #pragma unroll
                for (int jj = 0; jj < 4; jj++)
                    acc[ii][jj] += a[ii] * b[jj];
        }
        if (it + 1 < NIT) {
            #pragma unroll
            for (int q = 0; q < 4; q++)
                u.g.As[nxt][lcol + q][lrow] = ((const float*)&a_n)[q];
            *(float4*)&u.g.Bs[nxt][br][bc] = b_n;
            __syncthreads();
        }
    }

    float* outp = g_yp[z];
    #pragma unroll
    for (int ii = 0; ii < 4; ii++) {
        int r = m0 + ty * 4 + ii;
        #pragma unroll
        for (int jj = 0; jj < 4; jj++)
            outp[(size_t)r * DM + n0 + tx * 4 + jj] = acc[ii][jj];
    }
}

// ---------------------------------------------------------------------------
// Stage E: sum Y partials; ctx = Wv_h @ y + bv; MLP head. One block per batch.
// ---------------------------------------------------------------------------
__device__ __forceinline__ void stage_ctxmlp(int b, int tid, SMu& u,
                                             const float* __restrict__ Wv,
                                             const float* __restrict__ bv,
                                             const float* __restrict__ W1,
                                             const float* __restrict__ b1,
                                             const float* __restrict__ W2,
                                             const float* __restrict__ b2,
                                             float* __restrict__ out) {
    int w = tid >> 5, lane = tid & 31;

    for (int i4 = tid; i4 < NH * DM / 4; i4 += 256) {
        int h = i4 >> 7;
        int e4 = i4 & 127;
        float4 v = make_float4(0.f, 0.f, 0.f, 0.f);
        size_t off4 = ((size_t)(h * B_ + b) * DM) / 4 + e4;
        #pragma unroll
        for (int z = 0; z < YSPLIT; z++) {
            float4 p = ((const float4*)g_yp[z])[off4];
            v.x += p.x; v.y += p.y; v.z += p.z; v.w += p.w;
        }
        ((float4*)u.cm.ys[h])[e4] = v;
    }
    __syncthreads();

    const float* yv = u.cm.ys[w];
    for (int jj = 0; jj < DH; jj += 2) {
        int j0 = w * DH + jj;
        const float* w0 = Wv + (size_t)j0 * DM;
        const float* w1 = w0 + DM;
        float s0 = 0.f, s1 = 0.f;
        #pragma unroll
        for (int e0 = lane * 4; e0 < DM; e0 += 128) {
            float4 y4 = *(const float4*)(yv + e0);
            float4 a0 = *(const float4*)(w0 + e0);
            float4 a1 = *(const float4*)(w1 + e0);
            s0 += a0.x * y4.x + a0.y * y4.y + a0.z * y4.z + a0.w * y4.w;
            s1 += a1.x * y4.x + a1.y * y4.y + a1.z * y4.z + a1.w * y4.w;
        }
        #pragma unroll
        for (int off = 16; off; off >>= 1) {
            s0 += __shfl_xor_sync(0xffffffffu, s0, off);
            s1 += __shfl_xor_sync(0xffffffffu, s1, off);
        }
        if (lane == 0) {
            u.cm.cs[j0]     = s0 + bv[j0];
            u.cm.cs[j0 + 1] = s1 + bv[j0 + 1];
        }
    }
    __syncthreads();

    for (int jj = 0; jj < DH; jj += 2) {
        int j0 = w * DH + jj;
        const float* w0 = W1 + (size_t)j0 * DM;
        const float* w1 = w0 + DM;
        float s0 = 0.f, s1 = 0.f;
        #pragma unroll
        for (int e0 = lane * 4; e0 < DM; e0 += 128) {
            float4 c4 = *(const float4*)(u.cm.cs + e0);
            float4 a0 = *(const float4*)(w0 + e0);
            float4 a1 = *(const float4*)(w1 + e0);
            s0 += a0.x * c4.x + a0.y * c4.y + a0.z * c4.z + a0.w * c4.w;
            s1 += a1.x * c4.x + a1.y * c4.y + a1.z * c4.z + a1.w * c4.w;
        }
        #pragma unroll
        for (int off = 16; off; off >>= 1) {
            s0 += __shfl_xor_sync(0xffffffffu, s0, off);
            s1 += __shfl_xor_sync(0xffffffffu, s1, off);
        }
        if (lane == 0) {
            float v0 = s0 + b1[j0];
            float v1 = s1 + b1[j0 + 1];
            u.cm.hs[j0]     = (v0 > 0.f) ? v0 : 0.01f * v0;
            u.cm.hs[j0 + 1] = (v1 > 0.f) ? v1 : 0.01f * v1;
        }
    }
    __syncthreads();

    {
        const float* wr = W2 + (size_t)w * DM;
        float s = 0.f;
        #pragma unroll
        for (int e0 = lane * 4; e0 < DM; e0 += 128) {
            float4 a = *(const float4*)(wr + e0);
            float4 h4 = *(const float4*)(u.cm.hs + e0);
            s += a.x * h4.x + a.y * h4.y + a.z * h4.z + a.w * h4.w;
        }
        #pragma unroll
        for (int off = 16; off; off >>= 1) s += __shfl_xor_sync(0xffffffffu, s, off);
        if (lane == 0) {
            float v = s + b2[w];
            u.cm.o8[w] = (v > 0.f) ? v : 0.f;
        }
    }
    __syncthreads();
    if (tid == 0) {
        float mv = 0.f;
        #pragma unroll
        for (int k = 0; k < 8; k++) mv += u.cm.o8[k];
        mv *= 0.125f;
        out[b] = (mv > 0.f) ? mv : 0.01f * mv;
    }
}

// ---------------------------------------------------------------------------
// Megakernel: all stages, grid barriers between them.
// __launch_bounds__(256, 3): <=84 regs, 3 blocks/SM guaranteed
// -> 444 co-resident slots >= 320 blocks, so grid_barrier cannot deadlock.
// ---------------------------------------------------------------------------
__global__ void __launch_bounds__(256, 3)
mega_kernel(const int* __restrict__ data,
            const int* __restrict__ lengths,
            const float* __restrict__ emb,
            const float* __restrict__ Wq,
            const float* __restrict__ bq,
            const float* __restrict__ Wk,
            const float* __restrict__ Wv,
            const float* __restrict__ bv,
            const float* __restrict__ W1,
            const float* __restrict__ b1,
            const float* __restrict__ W2,
            const float* __restrict__ b2,
            float* __restrict__ out) {
    __shared__ SMu u;
    int blk = blockIdx.x;
    int tid = threadIdx.x;

    // Stage A: setup (414 logical blocks)
    for (int lb = blk; lb < SETUP_BLKS; lb += NBLK)
        stage_setup(lb, tid, u, data, lengths, emb, Wq, bq, Wk);
    grid_barrier();

    // Stage B: D GEMM (exactly NBLK logical blocks)
    stage_dgemm(blk, tid, u);
    grid_barrier();

    // Stage C: softmax + binning (256 logical blocks)
    if (blk < NI) stage_softmax(blk, tid, u, data, lengths);
    grid_barrier();

    // Stage D: Y GEMM (256 logical blocks)
    if (blk < 256) stage_ygemm(blk, tid, u);
    grid_barrier();

    // Stage E: ctx + MLP (32 logical blocks)
    if (blk < B_) stage_ctxmlp(blk, tid, u, Wv, bv, W1, b1, W2, b2, out);
}

// ---------------------------------------------------------------------------
extern "C" void kernel_launch(void* const* d_in, const int* in_sizes, int n_in,
                              void* d_out, int out_size) {
    const int* data    = (const int*)d_in[0];    // int32 (JAX x64 disabled)
    const int* lengths = (const int*)d_in[1];
    const float* emb = (const float*)d_in[2];
    const float* Wq  = (const float*)d_in[3];
    const float* bq  = (const float*)d_in[4];
    const float* Wk  = (const float*)d_in[5];
    // d_in[6] = bk: drops out of softmax (constant shift per row)
    const float* Wv  = (const float*)d_in[7];
    const float* bv  = (const float*)d_in[8];
    const float* W1  = (const float*)d_in[9];
    const float* b1  = (const float*)d_in[10];
    const float* W2  = (const float*)d_in[11];
    const float* b2  = (const float*)d_in[12];
    float* out = (float*)d_out;

    mega_kernel<<<NBLK, 256>>>(data, lengths, emb, Wq, bq, Wk,
                               Wv, bv, W1, b1, W2, b2, out);
}